// round 1
// baseline (speedup 1.0000x reference)
#include <cuda_runtime.h>
#include <cuda_bf16.h>
#include <math.h>

// Problem constants
#define Lc 15
#define Dc 512
#define Hc 64
#define HDc 8
#define Fc 2048
#define Gc 128
#define Bc 4
#define Nc 256
#define Mc (Bc*Nc)   // 1024 rows

// -------- scratch (device globals; no allocation allowed) --------
__device__ float g_h[Mc*Dc];
__device__ float g_x[Mc*Dc];
__device__ float g_qkv[Mc*3*Dc];
__device__ float g_attn[Mc*Dc];
__device__ float g_ffn[Mc*Fc];
__device__ float g_pair[Bc*Nc*Nc];

// ---------------- embedding ----------------
__global__ void emb_kernel(const int* __restrict__ atom_types,
                           const float* __restrict__ atom_emb,
                           float* __restrict__ h) {
    int idx = blockIdx.x * blockDim.x + threadIdx.x;   // Mc*Dc threads
    if (idx >= Mc*Dc) return;
    int row = idx >> 9;          // /512
    int d   = idx & 511;
    h[idx] = atom_emb[atom_types[row]*Dc + d];
}

// ---------------- pair representation ----------------
__global__ void pair_kernel(const float* __restrict__ coords,
                            const int* __restrict__ ptypes,
                            const float* __restrict__ pa,
                            const float* __restrict__ pb,
                            const float* __restrict__ mu,
                            const float* __restrict__ sigma,
                            const float* __restrict__ plw,
                            const float* __restrict__ plb,
                            float* __restrict__ pr) {
    __shared__ float smu[Gc], scoef[Gc];
    int tid = threadIdx.x;
    if (tid < Gc) {
        float sg = sigma[tid];
        // exp(...) / (2 sg^2) / (sg*sqrt(2pi)), folded with pl_w[g]
        scoef[tid] = plw[tid] / (2.0f*sg*sg) / (sg * 2.5066282746310002f);
        smu[tid]   = mu[tid];
    }
    __syncthreads();
    int p = blockIdx.x * blockDim.x + tid;             // B*N*N entries
    int b = p >> 16;
    int rem = p & 65535;
    int i = rem >> 8, j = rem & 255;
    const float* ci = coords + (b*Nc + i)*3;
    const float* cj = coords + (b*Nc + j)*3;
    float dx = ci[0]-cj[0], dy = ci[1]-cj[1], dz = ci[2]-cj[2];
    float d2 = dx*dx + dy*dy + dz*dz;
    float dist = sqrtf(fmaxf(d2, 1e-12f));
    int pt = ptypes[p];
    float da = pa[pt]*dist + pb[pt];
    float s = 0.f;
    #pragma unroll 8
    for (int g = 0; g < Gc; g++) {
        float t = da - smu[g];
        s += __expf(-t*t) * scoef[g];
    }
    pr[p] = s + plb[0];
}

// ---------------- layernorm ----------------
__global__ __launch_bounds__(128) void ln_kernel(const float* __restrict__ in,
                                                 const float* __restrict__ g,
                                                 const float* __restrict__ bb,
                                                 float* __restrict__ out) {
    int row = blockIdx.x;
    int tid = threadIdx.x;
    const float* x = in + row*Dc;
    float v[4], s = 0.f, s2 = 0.f;
    #pragma unroll
    for (int j = 0; j < 4; j++) {
        v[j] = x[tid + 128*j];
        s += v[j]; s2 += v[j]*v[j];
    }
    #pragma unroll
    for (int off = 16; off; off >>= 1) {
        s  += __shfl_xor_sync(0xffffffff, s,  off);
        s2 += __shfl_xor_sync(0xffffffff, s2, off);
    }
    __shared__ float rs[4], rs2[4];
    int wid = tid >> 5, lane = tid & 31;
    if (lane == 0) { rs[wid] = s; rs2[wid] = s2; }
    __syncthreads();
    s  = rs[0]+rs[1]+rs[2]+rs[3];
    s2 = rs2[0]+rs2[1]+rs2[2]+rs2[3];
    float mean = s * (1.0f/Dc);
    float var  = s2 * (1.0f/Dc) - mean*mean;
    float rstd = rsqrtf(var + 1e-5f);
    #pragma unroll
    for (int j = 0; j < 4; j++) {
        int d = tid + 128*j;
        out[row*Dc + d] = (v[j]-mean)*rstd*g[d] + bb[d];
    }
}

// ---------------- tiled fp32 GEMM: C = act(A @ W^T + bias) [+ res] ----------------
// A: MxK row-major, W: NxK row-major. M,N,K multiples of 64/16.
#define BM 64
#define BN 64
#define BK 16
__global__ __launch_bounds__(256) void gemm_kernel(const float* __restrict__ A,
                                                   const float* __restrict__ W,
                                                   const float* __restrict__ bias,
                                                   const float* __restrict__ res,
                                                   float* __restrict__ C,
                                                   int M, int N, int K, int act) {
    __shared__ float As[BK][BM];
    __shared__ float Ws[BK][BN];
    int tid = threadIdx.x;
    int tx = tid & 15, ty = tid >> 4;
    int m0 = blockIdx.y * BM, n0 = blockIdx.x * BN;
    int lr = tid >> 2;          // 0..63
    int lc = (tid & 3) * 4;     // 0,4,8,12
    float acc[4][4] = {};
    const float* Ap = A + (m0+lr)*K + lc;
    const float* Wp = W + (n0+lr)*K + lc;
    for (int k0 = 0; k0 < K; k0 += BK) {
        float4 av = *(const float4*)(Ap + k0);
        float4 wv = *(const float4*)(Wp + k0);
        As[lc+0][lr]=av.x; As[lc+1][lr]=av.y; As[lc+2][lr]=av.z; As[lc+3][lr]=av.w;
        Ws[lc+0][lr]=wv.x; Ws[lc+1][lr]=wv.y; Ws[lc+2][lr]=wv.z; Ws[lc+3][lr]=wv.w;
        __syncthreads();
        #pragma unroll
        for (int k = 0; k < BK; k++) {
            float4 a = *(const float4*)&As[k][ty*4];
            float4 b = *(const float4*)&Ws[k][tx*4];
            acc[0][0] += a.x*b.x; acc[0][1] += a.x*b.y; acc[0][2] += a.x*b.z; acc[0][3] += a.x*b.w;
            acc[1][0] += a.y*b.x; acc[1][1] += a.y*b.y; acc[1][2] += a.y*b.z; acc[1][3] += a.y*b.w;
            acc[2][0] += a.z*b.x; acc[2][1] += a.z*b.y; acc[2][2] += a.z*b.z; acc[2][3] += a.z*b.w;
            acc[3][0] += a.w*b.x; acc[3][1] += a.w*b.y; acc[3][2] += a.w*b.z; acc[3][3] += a.w*b.w;
        }
        __syncthreads();
    }
    #pragma unroll
    for (int i = 0; i < 4; i++) {
        int m = m0 + ty*4 + i;
        #pragma unroll
        for (int j = 0; j < 4; j++) {
            int n = n0 + tx*4 + j;
            float v = acc[i][j] + bias[n];
            if (act == 1) v = 0.5f * v * (1.0f + erff(v * 0.7071067811865475f));
            int idx = m*N + n;
            if (res) v += res[idx];
            C[idx] = v;
        }
    }
}

// ---------------- fused attention (scores + bias + softmax + PV) ----------------
__global__ __launch_bounds__(256) void attn_kernel(const float* __restrict__ qkv,
                                                   const float* __restrict__ pr,
                                                   const float* __restrict__ ppw,
                                                   const float* __restrict__ ppb,
                                                   float* __restrict__ out) {
    int b = blockIdx.x >> 6;
    int h = blockIdx.x & 63;
    __shared__ float Ks[Nc*9];   // padded stride 9 -> conflict-free
    __shared__ float Vs[Nc*9];
    int tid = threadIdx.x;
    {
        int n = tid;   // 256 threads, one K/V row each
        const float* kp = qkv + (((b*Nc + n)*3 + 1))*Dc + h*HDc;
        const float* vp = kp + Dc;
        float4 k0 = *(const float4*)kp,     k1 = *(const float4*)(kp+4);
        float4 v0 = *(const float4*)vp,     v1 = *(const float4*)(vp+4);
        float* kd = &Ks[n*9];
        kd[0]=k0.x; kd[1]=k0.y; kd[2]=k0.z; kd[3]=k0.w;
        kd[4]=k1.x; kd[5]=k1.y; kd[6]=k1.z; kd[7]=k1.w;
        float* vd = &Vs[n*9];
        vd[0]=v0.x; vd[1]=v0.y; vd[2]=v0.z; vd[3]=v0.w;
        vd[4]=v1.x; vd[5]=v1.y; vd[6]=v1.z; vd[7]=v1.w;
    }
    __syncthreads();
    const float scale = 0.3535533905932738f;   // 1/sqrt(8)
    float pw = ppw[h], pb = ppb[h];
    int warp = tid >> 5, lane = tid & 31;
    for (int r = 0; r < 32; r++) {
        int i = warp*32 + r;
        const float* qp = qkv + ((b*Nc + i)*3)*Dc + h*HDc;
        float4 q0 = *(const float4*)qp, q1 = *(const float4*)(qp+4);
        const float* prow = pr + (b*Nc + i)*Nc;
        float s[8];
        float mx = -1e30f;
        #pragma unroll
        for (int jj = 0; jj < 8; jj++) {
            int j = lane + 32*jj;
            const float* kk = &Ks[j*9];
            float d = q0.x*kk[0] + q0.y*kk[1] + q0.z*kk[2] + q0.w*kk[3]
                    + q1.x*kk[4] + q1.y*kk[5] + q1.z*kk[6] + q1.w*kk[7];
            s[jj] = d*scale + prow[j]*pw + pb;
            mx = fmaxf(mx, s[jj]);
        }
        #pragma unroll
        for (int off = 16; off; off >>= 1)
            mx = fmaxf(mx, __shfl_xor_sync(0xffffffff, mx, off));
        float sum = 0.f;
        #pragma unroll
        for (int jj = 0; jj < 8; jj++) { s[jj] = __expf(s[jj]-mx); sum += s[jj]; }
        #pragma unroll
        for (int off = 16; off; off >>= 1)
            sum += __shfl_xor_sync(0xffffffff, sum, off);
        float inv = 1.0f / sum;
        float acc[8] = {};
        #pragma unroll
        for (int jj = 0; jj < 8; jj++) {
            int j = lane + 32*jj;
            float p = s[jj]*inv;
            const float* vv = &Vs[j*9];
            #pragma unroll
            for (int d = 0; d < 8; d++) acc[d] += p*vv[d];
        }
        #pragma unroll
        for (int off = 16; off; off >>= 1) {
            #pragma unroll
            for (int d = 0; d < 8; d++)
                acc[d] += __shfl_xor_sync(0xffffffff, acc[d], off);
        }
        if (lane == 0) {
            float* op = out + (b*Nc + i)*Dc + h*HDc;
            #pragma unroll
            for (int d = 0; d < 8; d++) op[d] = acc[d];
        }
    }
}

// ---------------- SE(3) coordinate update ----------------
__global__ __launch_bounds__(128) void coords_kernel(const float* __restrict__ coords,
                                                     const float* __restrict__ pr,
                                                     const float* __restrict__ uw,
                                                     const float* __restrict__ ub,
                                                     const float* __restrict__ ww,
                                                     const float* __restrict__ wb,
                                                     float* __restrict__ out) {
    int gw = blockIdx.x * 4 + (threadIdx.x >> 5);  // global warp -> (b,i)
    int lane = threadIdx.x & 31;
    int b = gw >> 8, i = gw & 255;
    float u0 = uw[0], u1 = ub[0], w0 = ww[0], w1 = wb[0];
    const float* ci = coords + (b*Nc + i)*3;
    float cx = ci[0], cy = ci[1], cz = ci[2];
    float ax = 0.f, ay = 0.f, az = 0.f;
    const float* prow = pr + (b*Nc + i)*Nc;
    #pragma unroll
    for (int jj = 0; jj < 8; jj++) {
        int j = lane + 32*jj;
        const float* cj = coords + (b*Nc + j)*3;
        float c = (fmaxf(prow[j], 0.f)*u0 + u1)*w0 + w1;
        ax += (cx - cj[0])*c;
        ay += (cy - cj[1])*c;
        az += (cz - cj[2])*c;
    }
    #pragma unroll
    for (int off = 16; off; off >>= 1) {
        ax += __shfl_xor_sync(0xffffffff, ax, off);
        ay += __shfl_xor_sync(0xffffffff, ay, off);
        az += __shfl_xor_sync(0xffffffff, az, off);
    }
    if (lane == 0) {
        float invn = 1.0f / (256.0f + 1e-6f);
        float* op = out + (b*Nc + i)*3;
        op[0] = cx + ax*invn;
        op[1] = cy + ay*invn;
        op[2] = cz + az*invn;
    }
}

// ---------------- energy head ----------------
__global__ __launch_bounds__(128) void energy_kernel(const float* __restrict__ h,
                                                     const float* __restrict__ enw,
                                                     const float* __restrict__ enb,
                                                     float* __restrict__ out) {
    int b = blockIdx.x;
    int tid = threadIdx.x;
    const float* row = h + (b*Nc)*Dc;   // token 0
    float s = 0.f;
    #pragma unroll
    for (int j = 0; j < 4; j++) {
        int d = tid + 128*j;
        s += row[d]*enw[d];
    }
    #pragma unroll
    for (int off = 16; off; off >>= 1)
        s += __shfl_xor_sync(0xffffffff, s, off);
    __shared__ float rs[4];
    int wid = tid >> 5, lane = tid & 31;
    if (lane == 0) rs[wid] = s;
    __syncthreads();
    if (tid == 0)
        out[Bc*Nc*3 + b] = rs[0]+rs[1]+rs[2]+rs[3] + enb[0];
}

// ---------------- host ----------------
extern "C" void kernel_launch(void* const* d_in, const int* in_sizes, int n_in,
                              void* d_out, int out_size) {
    // Input indexing robust to whether the bool mask tensor is materialized.
    bool has_mask = (n_in >= 31);
    auto IN = [&](int i) -> const void* {
        int k = i;
        if (!has_mask && i > 3) k = i - 1;
        return d_in[k];
    };
    const int*   atom_types = (const int*)  IN(0);
    const float* coords     = (const float*)IN(1);
    const int*   pair_types = (const int*)  IN(2);
    const float* atom_emb   = (const float*)IN(4);
    const float* gmu        = (const float*)IN(5);
    const float* gsigma     = (const float*)IN(6);
    const float* pair_a     = (const float*)IN(7);
    const float* pair_b     = (const float*)IN(8);
    const float* pl_w       = (const float*)IN(9);
    const float* pl_b       = (const float*)IN(10);
    const float* ln1_g      = (const float*)IN(11);
    const float* ln1_b      = (const float*)IN(12);
    const float* qkv_w      = (const float*)IN(13);
    const float* qkv_b      = (const float*)IN(14);
    const float* pp_w       = (const float*)IN(15);
    const float* pp_b       = (const float*)IN(16);
    const float* out_w      = (const float*)IN(17);
    const float* out_b      = (const float*)IN(18);
    const float* ln2_g      = (const float*)IN(19);
    const float* ln2_b      = (const float*)IN(20);
    const float* ffn_w1     = (const float*)IN(21);
    const float* ffn_b1     = (const float*)IN(22);
    const float* ffn_w2     = (const float*)IN(23);
    const float* ffn_b2     = (const float*)IN(24);
    const float* se3_uw     = (const float*)IN(25);
    const float* se3_ub     = (const float*)IN(26);
    const float* se3_ww     = (const float*)IN(27);
    const float* se3_wb     = (const float*)IN(28);
    const float* en_w       = (const float*)IN(29);
    const float* en_b       = (const float*)IN(30);
    float* out = (float*)d_out;

    float *hb, *xb, *qkvb, *attnb, *ffnb, *pairb;
    cudaGetSymbolAddress((void**)&hb,    g_h);
    cudaGetSymbolAddress((void**)&xb,    g_x);
    cudaGetSymbolAddress((void**)&qkvb,  g_qkv);
    cudaGetSymbolAddress((void**)&attnb, g_attn);
    cudaGetSymbolAddress((void**)&ffnb,  g_ffn);
    cudaGetSymbolAddress((void**)&pairb, g_pair);

    emb_kernel<<<(Mc*Dc + 255)/256, 256>>>(atom_types, atom_emb, hb);
    pair_kernel<<<(Bc*Nc*Nc)/256, 256>>>(coords, pair_types, pair_a, pair_b,
                                         gmu, gsigma, pl_w, pl_b, pairb);

    for (int l = 0; l < Lc; l++) {
        const float* l1g = ln1_g + l*Dc;
        const float* l1b = ln1_b + l*Dc;
        const float* qw  = qkv_w + (size_t)l*3*Dc*Dc;
        const float* qb  = qkv_b + l*3*Dc;
        const float* pwp = pp_w + l*Hc;
        const float* pbp = pp_b + l*Hc;
        const float* ow  = out_w + (size_t)l*Dc*Dc;
        const float* ob  = out_b + l*Dc;
        const float* l2g = ln2_g + l*Dc;
        const float* l2b = ln2_b + l*Dc;
        const float* w1  = ffn_w1 + (size_t)l*Fc*Dc;
        const float* b1  = ffn_b1 + l*Fc;
        const float* w2  = ffn_w2 + (size_t)l*Dc*Fc;
        const float* b2  = ffn_b2 + l*Dc;

        ln_kernel<<<Mc, 128>>>(hb, l1g, l1b, xb);
        gemm_kernel<<<dim3((3*Dc)/BN, Mc/BM), 256>>>(xb, qw, qb, nullptr, qkvb,
                                                     Mc, 3*Dc, Dc, 0);
        attn_kernel<<<Bc*Hc, 256>>>(qkvb, pairb, pwp, pbp, attnb);
        gemm_kernel<<<dim3(Dc/BN, Mc/BM), 256>>>(attnb, ow, ob, hb, hb,
                                                 Mc, Dc, Dc, 0);
        ln_kernel<<<Mc, 128>>>(hb, l2g, l2b, xb);
        gemm_kernel<<<dim3(Fc/BN, Mc/BM), 256>>>(xb, w1, b1, nullptr, ffnb,
                                                 Mc, Fc, Dc, 1);
        gemm_kernel<<<dim3(Dc/BN, Mc/BM), 256>>>(ffnb, w2, b2, hb, hb,
                                                 Mc, Dc, Fc, 0);
    }

    coords_kernel<<<(Bc*Nc)/4, 128>>>(coords, pairb, se3_uw, se3_ub, se3_ww, se3_wb, out);
    energy_kernel<<<Bc, 128>>>(hb, en_w, en_b, out);
    (void)in_sizes; (void)out_size;
}

// round 2
// speedup vs baseline: 1.3528x; 1.3528x over previous
#include <cuda_runtime.h>
#include <cuda_bf16.h>
#include <math.h>

// Problem constants
#define Lc 15
#define Dc 512
#define Hc 64
#define HDc 8
#define Fc 2048
#define Gc 128
#define Bc 4
#define Nc 256
#define Mc (Bc*Nc)   // 1024 rows
#define SPLITK 4

// -------- scratch (device globals; no allocation allowed) --------
__device__ float g_h[Mc*Dc];
__device__ float g_x[Mc*Dc];
__device__ float g_qkv[Mc*3*Dc];
__device__ float g_attn[Mc*Dc];
__device__ float g_ffn[Mc*Fc];
__device__ float g_pair[Bc*Nc*Nc];
__device__ float g_split[SPLITK*Mc*Dc];

// ---------------- embedding ----------------
__global__ void emb_kernel(const int* __restrict__ atom_types,
                           const float* __restrict__ atom_emb,
                           float* __restrict__ h) {
    int idx = blockIdx.x * blockDim.x + threadIdx.x;   // Mc*Dc threads
    if (idx >= Mc*Dc) return;
    int row = idx >> 9;          // /512
    int d   = idx & 511;
    h[idx] = atom_emb[atom_types[row]*Dc + d];
}

// ---------------- pair representation ----------------
__global__ void pair_kernel(const float* __restrict__ coords,
                            const int* __restrict__ ptypes,
                            const float* __restrict__ pa,
                            const float* __restrict__ pb,
                            const float* __restrict__ mu,
                            const float* __restrict__ sigma,
                            const float* __restrict__ plw,
                            const float* __restrict__ plb,
                            float* __restrict__ pr) {
    __shared__ float smu[Gc], scoef[Gc];
    int tid = threadIdx.x;
    if (tid < Gc) {
        float sg = sigma[tid];
        scoef[tid] = plw[tid] / (2.0f*sg*sg) / (sg * 2.5066282746310002f);
        smu[tid]   = mu[tid];
    }
    __syncthreads();
    int p = blockIdx.x * blockDim.x + tid;             // B*N*N entries
    int b = p >> 16;
    int rem = p & 65535;
    int i = rem >> 8, j = rem & 255;
    const float* ci = coords + (b*Nc + i)*3;
    const float* cj = coords + (b*Nc + j)*3;
    float dx = ci[0]-cj[0], dy = ci[1]-cj[1], dz = ci[2]-cj[2];
    float d2 = dx*dx + dy*dy + dz*dz;
    float dist = sqrtf(fmaxf(d2, 1e-12f));
    int pt = ptypes[p];
    float da = pa[pt]*dist + pb[pt];
    float s = 0.f;
    #pragma unroll 8
    for (int g = 0; g < Gc; g++) {
        float t = da - smu[g];
        s += __expf(-t*t) * scoef[g];
    }
    pr[p] = s + plb[0];
}

// ---------------- layernorm ----------------
__global__ __launch_bounds__(128) void ln_kernel(const float* __restrict__ in,
                                                 const float* __restrict__ g,
                                                 const float* __restrict__ bb,
                                                 float* __restrict__ out) {
    int row = blockIdx.x;
    int tid = threadIdx.x;
    const float* x = in + row*Dc;
    float v[4], s = 0.f, s2 = 0.f;
    #pragma unroll
    for (int j = 0; j < 4; j++) {
        v[j] = x[tid + 128*j];
        s += v[j]; s2 += v[j]*v[j];
    }
    #pragma unroll
    for (int off = 16; off; off >>= 1) {
        s  += __shfl_xor_sync(0xffffffff, s,  off);
        s2 += __shfl_xor_sync(0xffffffff, s2, off);
    }
    __shared__ float rs[4], rs2[4];
    int wid = tid >> 5, lane = tid & 31;
    if (lane == 0) { rs[wid] = s; rs2[wid] = s2; }
    __syncthreads();
    s  = rs[0]+rs[1]+rs[2]+rs[3];
    s2 = rs2[0]+rs2[1]+rs2[2]+rs2[3];
    float mean = s * (1.0f/Dc);
    float var  = s2 * (1.0f/Dc) - mean*mean;
    float rstd = rsqrtf(var + 1e-5f);
    #pragma unroll
    for (int j = 0; j < 4; j++) {
        int d = tid + 128*j;
        out[row*Dc + d] = (v[j]-mean)*rstd*g[d] + bb[d];
    }
}

// ---------------- 128x128x16 fp32 GEMM, 8x8 per thread ----------------
// C = act(A @ W^T + bias) [+ res]    (A: MxK, W: NxK, both row-major)
// If gridDim.z > 1: K is sliced over z, pure partials are written to
// C + z*M*N with no epilogue (bias/res must then be applied in reduce).
#define GBM 128
#define GBN 128
#define GBK 16
__global__ __launch_bounds__(256) void gemm128_kernel(
    const float* __restrict__ A, const float* __restrict__ W,
    const float* __restrict__ bias, const float* __restrict__ res,
    float* __restrict__ C, int M, int N, int K, int act)
{
    __shared__ float As[GBK][GBM+4];
    __shared__ float Ws[GBK][GBN+4];
    int tid = threadIdx.x;
    int m0 = blockIdx.y*GBM, n0 = blockIdx.x*GBN;
    int S = gridDim.z;
    int Ks = K / S;
    int kbeg = blockIdx.z * Ks;
    int lr = tid >> 2;          // 0..63
    int lc = (tid & 3) * 4;     // 0,4,8,12
    const float* Ap = A + (size_t)(m0 + lr)*K + kbeg + lc;
    const float* Wp = W + (size_t)(n0 + lr)*K + kbeg + lc;
    int ty = tid >> 4, tx = tid & 15;

    float acc[8][8] = {};
    // stage first tile
    float4 a0 = *(const float4*)(Ap);
    float4 a1 = *(const float4*)(Ap + (size_t)64*K);
    float4 w0 = *(const float4*)(Wp);
    float4 w1 = *(const float4*)(Wp + (size_t)64*K);

    for (int k0 = 0; k0 < Ks; k0 += GBK) {
        As[lc+0][lr]    = a0.x; As[lc+1][lr]    = a0.y; As[lc+2][lr]    = a0.z; As[lc+3][lr]    = a0.w;
        As[lc+0][lr+64] = a1.x; As[lc+1][lr+64] = a1.y; As[lc+2][lr+64] = a1.z; As[lc+3][lr+64] = a1.w;
        Ws[lc+0][lr]    = w0.x; Ws[lc+1][lr]    = w0.y; Ws[lc+2][lr]    = w0.z; Ws[lc+3][lr]    = w0.w;
        Ws[lc+0][lr+64] = w1.x; Ws[lc+1][lr+64] = w1.y; Ws[lc+2][lr+64] = w1.z; Ws[lc+3][lr+64] = w1.w;
        __syncthreads();
        if (k0 + GBK < Ks) {
            a0 = *(const float4*)(Ap + k0 + GBK);
            a1 = *(const float4*)(Ap + k0 + GBK + (size_t)64*K);
            w0 = *(const float4*)(Wp + k0 + GBK);
            w1 = *(const float4*)(Wp + k0 + GBK + (size_t)64*K);
        }
        #pragma unroll
        for (int k = 0; k < GBK; k++) {
            float ar[8], br[8];
            *(float4*)(ar)   = *(const float4*)&As[k][ty*8];
            *(float4*)(ar+4) = *(const float4*)&As[k][ty*8+4];
            *(float4*)(br)   = *(const float4*)&Ws[k][tx*8];
            *(float4*)(br+4) = *(const float4*)&Ws[k][tx*8+4];
            #pragma unroll
            for (int i = 0; i < 8; i++)
                #pragma unroll
                for (int j = 0; j < 8; j++)
                    acc[i][j] += ar[i]*br[j];
        }
        __syncthreads();
    }

    if (S > 1) {
        // pure partial: C + z*M*N
        float* Cp = C + (size_t)blockIdx.z*M*N;
        #pragma unroll
        for (int i = 0; i < 8; i++) {
            int m = m0 + ty*8 + i;
            float* dst = Cp + (size_t)m*N + n0 + tx*8;
            *(float4*)(dst)   = *(float4*)&acc[i][0];
            *(float4*)(dst+4) = *(float4*)&acc[i][4];
        }
    } else {
        #pragma unroll
        for (int i = 0; i < 8; i++) {
            int m = m0 + ty*8 + i;
            float vr[8];
            #pragma unroll
            for (int j = 0; j < 8; j++) {
                int n = n0 + tx*8 + j;
                float v = acc[i][j] + bias[n];
                if (act == 1) v = 0.5f * v * (1.0f + erff(v * 0.7071067811865475f));
                vr[j] = v;
            }
            float* dst = C + (size_t)m*N + n0 + tx*8;
            if (res) {
                const float* rp = res + (size_t)m*N + n0 + tx*8;
                float4 r0 = *(const float4*)(rp);
                float4 r1 = *(const float4*)(rp+4);
                vr[0]+=r0.x; vr[1]+=r0.y; vr[2]+=r0.z; vr[3]+=r0.w;
                vr[4]+=r1.x; vr[5]+=r1.y; vr[6]+=r1.z; vr[7]+=r1.w;
            }
            *(float4*)(dst)   = *(float4*)&vr[0];
            *(float4*)(dst+4) = *(float4*)&vr[4];
        }
    }
}

// ---------------- split-K reduce: h += sum_z partial[z] + bias ----------------
__global__ __launch_bounds__(256) void reduce_splitk(const float* __restrict__ P,
                                                     const float* __restrict__ bias,
                                                     float* __restrict__ h,
                                                     int MN, int N) {
    int i4 = blockIdx.x*256 + threadIdx.x;
    if (i4 >= MN/4) return;
    int n = (i4*4) & (N-1);   // N is a power of 2
    const float4* P4 = (const float4*)P;
    int stride4 = MN/4;
    float4 s0 = P4[i4];
    float4 s1 = P4[i4 + stride4];
    float4 s2 = P4[i4 + 2*stride4];
    float4 s3 = P4[i4 + 3*stride4];
    float4 b  = *(const float4*)(bias + n);
    float4 hv = ((float4*)h)[i4];
    hv.x += s0.x + s1.x + s2.x + s3.x + b.x;
    hv.y += s0.y + s1.y + s2.y + s3.y + b.y;
    hv.z += s0.z + s1.z + s2.z + s3.z + b.z;
    hv.w += s0.w + s1.w + s2.w + s3.w + b.w;
    ((float4*)h)[i4] = hv;
}

// ---------------- fused attention (scores + bias + softmax + PV) ----------------
// grid: (Bc*Hc, 8), 256 threads; each warp handles 4 query rows.
__global__ __launch_bounds__(256) void attn_kernel(const float* __restrict__ qkv,
                                                   const float* __restrict__ pr,
                                                   const float* __restrict__ ppw,
                                                   const float* __restrict__ ppb,
                                                   float* __restrict__ out) {
    int b = blockIdx.x >> 6;
    int h = blockIdx.x & 63;
    __shared__ float Ks[Nc*9];   // padded stride 9 -> conflict-free
    __shared__ float Vs[Nc*9];
    int tid = threadIdx.x;
    {
        int n = tid;   // 256 threads, one K/V row each
        const float* kp = qkv + (((b*Nc + n)*3 + 1))*Dc + h*HDc;
        const float* vp = kp + Dc;
        float4 k0 = *(const float4*)kp,     k1 = *(const float4*)(kp+4);
        float4 v0 = *(const float4*)vp,     v1 = *(const float4*)(vp+4);
        float* kd = &Ks[n*9];
        kd[0]=k0.x; kd[1]=k0.y; kd[2]=k0.z; kd[3]=k0.w;
        kd[4]=k1.x; kd[5]=k1.y; kd[6]=k1.z; kd[7]=k1.w;
        float* vd = &Vs[n*9];
        vd[0]=v0.x; vd[1]=v0.y; vd[2]=v0.z; vd[3]=v0.w;
        vd[4]=v1.x; vd[5]=v1.y; vd[6]=v1.z; vd[7]=v1.w;
    }
    __syncthreads();
    const float scale = 0.3535533905932738f;   // 1/sqrt(8)
    float pw = ppw[h], pb = ppb[h];
    int warp = tid >> 5, lane = tid & 31;
    #pragma unroll
    for (int r = 0; r < 4; r++) {
        int i = blockIdx.y*32 + warp*4 + r;
        const float* qp = qkv + ((b*Nc + i)*3)*Dc + h*HDc;
        float4 q0 = *(const float4*)qp, q1 = *(const float4*)(qp+4);
        const float* prow = pr + (b*Nc + i)*Nc;
        float s[8];
        float mx = -1e30f;
        #pragma unroll
        for (int jj = 0; jj < 8; jj++) {
            int j = lane + 32*jj;
            const float* kk = &Ks[j*9];
            float d = q0.x*kk[0] + q0.y*kk[1] + q0.z*kk[2] + q0.w*kk[3]
                    + q1.x*kk[4] + q1.y*kk[5] + q1.z*kk[6] + q1.w*kk[7];
            s[jj] = d*scale + prow[j]*pw + pb;
            mx = fmaxf(mx, s[jj]);
        }
        #pragma unroll
        for (int off = 16; off; off >>= 1)
            mx = fmaxf(mx, __shfl_xor_sync(0xffffffff, mx, off));
        float sum = 0.f;
        #pragma unroll
        for (int jj = 0; jj < 8; jj++) { s[jj] = __expf(s[jj]-mx); sum += s[jj]; }
        #pragma unroll
        for (int off = 16; off; off >>= 1)
            sum += __shfl_xor_sync(0xffffffff, sum, off);
        float inv = 1.0f / sum;
        float acc[8] = {};
        #pragma unroll
        for (int jj = 0; jj < 8; jj++) {
            int j = lane + 32*jj;
            float p = s[jj]*inv;
            const float* vv = &Vs[j*9];
            #pragma unroll
            for (int d = 0; d < 8; d++) acc[d] += p*vv[d];
        }
        #pragma unroll
        for (int off = 16; off; off >>= 1) {
            #pragma unroll
            for (int d = 0; d < 8; d++)
                acc[d] += __shfl_xor_sync(0xffffffff, acc[d], off);
        }
        if (lane == 0) {
            float* op = out + (b*Nc + i)*Dc + h*HDc;
            #pragma unroll
            for (int d = 0; d < 8; d++) op[d] = acc[d];
        }
    }
}

// ---------------- SE(3) coordinate update ----------------
__global__ __launch_bounds__(128) void coords_kernel(const float* __restrict__ coords,
                                                     const float* __restrict__ pr,
                                                     const float* __restrict__ uw,
                                                     const float* __restrict__ ub,
                                                     const float* __restrict__ ww,
                                                     const float* __restrict__ wb,
                                                     float* __restrict__ out) {
    int gw = blockIdx.x * 4 + (threadIdx.x >> 5);  // global warp -> (b,i)
    int lane = threadIdx.x & 31;
    int b = gw >> 8, i = gw & 255;
    float u0 = uw[0], u1 = ub[0], w0 = ww[0], w1 = wb[0];
    const float* ci = coords + (b*Nc + i)*3;
    float cx = ci[0], cy = ci[1], cz = ci[2];
    float ax = 0.f, ay = 0.f, az = 0.f;
    const float* prow = pr + (b*Nc + i)*Nc;
    #pragma unroll
    for (int jj = 0; jj < 8; jj++) {
        int j = lane + 32*jj;
        const float* cj = coords + (b*Nc + j)*3;
        float c = (fmaxf(prow[j], 0.f)*u0 + u1)*w0 + w1;
        ax += (cx - cj[0])*c;
        ay += (cy - cj[1])*c;
        az += (cz - cj[2])*c;
    }
    #pragma unroll
    for (int off = 16; off; off >>= 1) {
        ax += __shfl_xor_sync(0xffffffff, ax, off);
        ay += __shfl_xor_sync(0xffffffff, ay, off);
        az += __shfl_xor_sync(0xffffffff, az, off);
    }
    if (lane == 0) {
        float invn = 1.0f / (256.0f + 1e-6f);
        float* op = out + (b*Nc + i)*3;
        op[0] = cx + ax*invn;
        op[1] = cy + ay*invn;
        op[2] = cz + az*invn;
    }
}

// ---------------- energy head ----------------
__global__ __launch_bounds__(128) void energy_kernel(const float* __restrict__ h,
                                                     const float* __restrict__ enw,
                                                     const float* __restrict__ enb,
                                                     float* __restrict__ out) {
    int b = blockIdx.x;
    int tid = threadIdx.x;
    const float* row = h + (b*Nc)*Dc;   // token 0
    float s = 0.f;
    #pragma unroll
    for (int j = 0; j < 4; j++) {
        int d = tid + 128*j;
        s += row[d]*enw[d];
    }
    #pragma unroll
    for (int off = 16; off; off >>= 1)
        s += __shfl_xor_sync(0xffffffff, s, off);
    __shared__ float rs[4];
    int wid = tid >> 5, lane = tid & 31;
    if (lane == 0) rs[wid] = s;
    __syncthreads();
    if (tid == 0)
        out[Bc*Nc*3 + b] = rs[0]+rs[1]+rs[2]+rs[3] + enb[0];
}

// ---------------- host ----------------
extern "C" void kernel_launch(void* const* d_in, const int* in_sizes, int n_in,
                              void* d_out, int out_size) {
    bool has_mask = (n_in >= 31);
    auto IN = [&](int i) -> const void* {
        int k = i;
        if (!has_mask && i > 3) k = i - 1;
        return d_in[k];
    };
    const int*   atom_types = (const int*)  IN(0);
    const float* coords     = (const float*)IN(1);
    const int*   pair_types = (const int*)  IN(2);
    const float* atom_emb   = (const float*)IN(4);
    const float* gmu        = (const float*)IN(5);
    const float* gsigma     = (const float*)IN(6);
    const float* pair_a     = (const float*)IN(7);
    const float* pair_b     = (const float*)IN(8);
    const float* pl_w       = (const float*)IN(9);
    const float* pl_b       = (const float*)IN(10);
    const float* ln1_g      = (const float*)IN(11);
    const float* ln1_b      = (const float*)IN(12);
    const float* qkv_w      = (const float*)IN(13);
    const float* qkv_b      = (const float*)IN(14);
    const float* pp_w       = (const float*)IN(15);
    const float* pp_b       = (const float*)IN(16);
    const float* out_w      = (const float*)IN(17);
    const float* out_b      = (const float*)IN(18);
    const float* ln2_g      = (const float*)IN(19);
    const float* ln2_b      = (const float*)IN(20);
    const float* ffn_w1     = (const float*)IN(21);
    const float* ffn_b1     = (const float*)IN(22);
    const float* ffn_w2     = (const float*)IN(23);
    const float* ffn_b2     = (const float*)IN(24);
    const float* se3_uw     = (const float*)IN(25);
    const float* se3_ub     = (const float*)IN(26);
    const float* se3_ww     = (const float*)IN(27);
    const float* se3_wb     = (const float*)IN(28);
    const float* en_w       = (const float*)IN(29);
    const float* en_b       = (const float*)IN(30);
    float* out = (float*)d_out;

    float *hb, *xb, *qkvb, *attnb, *ffnb, *pairb, *splitb;
    cudaGetSymbolAddress((void**)&hb,     g_h);
    cudaGetSymbolAddress((void**)&xb,     g_x);
    cudaGetSymbolAddress((void**)&qkvb,   g_qkv);
    cudaGetSymbolAddress((void**)&attnb,  g_attn);
    cudaGetSymbolAddress((void**)&ffnb,   g_ffn);
    cudaGetSymbolAddress((void**)&pairb,  g_pair);
    cudaGetSymbolAddress((void**)&splitb, g_split);

    emb_kernel<<<(Mc*Dc + 255)/256, 256>>>(atom_types, atom_emb, hb);
    pair_kernel<<<(Bc*Nc*Nc)/256, 256>>>(coords, pair_types, pair_a, pair_b,
                                         gmu, gsigma, pl_w, pl_b, pairb);

    for (int l = 0; l < Lc; l++) {
        const float* l1g = ln1_g + l*Dc;
        const float* l1b = ln1_b + l*Dc;
        const float* qw  = qkv_w + (size_t)l*3*Dc*Dc;
        const float* qb  = qkv_b + l*3*Dc;
        const float* pwp = pp_w + l*Hc;
        const float* pbp = pp_b + l*Hc;
        const float* ow  = out_w + (size_t)l*Dc*Dc;
        const float* ob  = out_b + l*Dc;
        const float* l2g = ln2_g + l*Dc;
        const float* l2b = ln2_b + l*Dc;
        const float* w1  = ffn_w1 + (size_t)l*Fc*Dc;
        const float* b1  = ffn_b1 + l*Fc;
        const float* w2  = ffn_w2 + (size_t)l*Dc*Fc;
        const float* b2  = ffn_b2 + l*Dc;

        ln_kernel<<<Mc, 128>>>(hb, l1g, l1b, xb);
        gemm128_kernel<<<dim3((3*Dc)/GBN, Mc/GBM, 1), 256>>>(xb, qw, qb, nullptr, qkvb,
                                                             Mc, 3*Dc, Dc, 0);
        attn_kernel<<<dim3(Bc*Hc, 8), 256>>>(qkvb, pairb, pwp, pbp, attnb);
        gemm128_kernel<<<dim3(Dc/GBN, Mc/GBM, SPLITK), 256>>>(attnb, ow, nullptr, nullptr,
                                                              splitb, Mc, Dc, Dc, 0);
        reduce_splitk<<<(Mc*Dc/4 + 255)/256, 256>>>(splitb, ob, hb, Mc*Dc, Dc);
        ln_kernel<<<Mc, 128>>>(hb, l2g, l2b, xb);
        gemm128_kernel<<<dim3(Fc/GBN, Mc/GBM, 1), 256>>>(xb, w1, b1, nullptr, ffnb,
                                                         Mc, Fc, Dc, 1);
        gemm128_kernel<<<dim3(Dc/GBN, Mc/GBM, SPLITK), 256>>>(ffnb, w2, nullptr, nullptr,
                                                              splitb, Mc, Dc, Fc, 0);
        reduce_splitk<<<(Mc*Dc/4 + 255)/256, 256>>>(splitb, b2, hb, Mc*Dc, Dc);
    }

    coords_kernel<<<(Bc*Nc)/4, 128>>>(coords, pairb, se3_uw, se3_ub, se3_ww, se3_wb, out);
    energy_kernel<<<Bc, 128>>>(hb, en_w, en_b, out);
    (void)in_sizes; (void)out_size;
}